// round 1
// baseline (speedup 1.0000x reference)
#include <cuda_runtime.h>

// Problem constants
#define NB     8
#define NH     16
#define NS     2048
#define DD     64
#define HI     256
#define NITN   4
#define CHUNK  512
#define MT     32
#define NTILE  (CHUNK / MT)          // 16
#define INV_SC (1.0f / 32768.0f)     // 1/(chunk*D)

// Final adapted weights per (b,h): [128][W1(64*256) | W2(256*64)]
__device__ float g_W[NB * NH * (DD * HI + HI * DD)];

// ---------------- gelu (tanh approximation, matches jax.nn.gelu default) ----
__device__ __forceinline__ float gelu_fwd_bwd(float x, float* dg) {
    const float c0 = 0.7978845608028654f;   // sqrt(2/pi)
    const float a0 = 0.044715f;
    float x2 = x * x;
    float u  = c0 * x * fmaf(a0, x2, 1.0f);
    float t  = tanhf(u);
    float du = c0 * fmaf(3.0f * a0, x2, 1.0f);
    *dg = 0.5f * (1.0f + t) + 0.5f * x * (1.0f - t * t) * du;
    return 0.5f * x * (1.0f + t);
}
__device__ __forceinline__ float gelu_f(float x) {
    const float c0 = 0.7978845608028654f;
    const float a0 = 0.044715f;
    float u = c0 * x * fmaf(a0, x * x, 1.0f);
    return 0.5f * x * (1.0f + tanhf(u));
}

// ---------------- SMEM layout (floats), training kernel ---------------------
// sW1 : [64][256]          @ 0      (16384)
// sW2 : [256][65] (padded) @ 16384  (16640)
// sZ  : [32][256] Z->H->dZ @ 33024  (8192)
// sGp : [32][256] gelu'    @ 41216  (8192)
// sX  : [32][64]           @ 49408  (2048)
// sY  : [32][64]           @ 51456  (2048)
// sE  : [32][64]           @ 53504  (2048)
// total 55552 floats = 222208 bytes
#define TRAIN_SMEM_BYTES 222208
#define EVAL_SMEM_BYTES  212992

__global__ __launch_bounds__(256, 1)
void ttt_train_kernel(const float* __restrict__ kk, const float* __restrict__ vv,
                      const float* __restrict__ W1g, const float* __restrict__ W2g) {
    extern __shared__ float sm[];
    float* sW1 = sm;              // [64][256]
    float* sW2 = sm + 16384;      // [256][65]
    float* sZ  = sm + 33024;      // [32][256]
    float* sGp = sm + 41216;      // [32][256]
    float* sX  = sm + 49408;      // [32][64]
    float* sY  = sm + 51456;      // [32][64]
    float* sE  = sm + 53504;      // [32][64]

    const int bh   = blockIdx.x;        // b*NH + h
    const int h    = bh & (NH - 1);
    const int tid  = threadIdx.x;
    const int lane = tid & 31;
    const int rg   = tid >> 5;          // 0..7

    // Load initial weights (same for every b)
    const float* gW1 = W1g + (size_t)h * DD * HI;
    const float* gW2 = W2g + (size_t)h * HI * DD;
    for (int i = tid; i < DD * HI; i += 256) sW1[i] = gW1[i];
    for (int i = tid; i < HI * DD; i += 256) {
        int e = i >> 6, o = i & 63;
        sW2[e * 65 + o] = gW2[i];
    }
    __syncthreads();

    const float* kb = kk + (size_t)bh * NS * DD;
    const float* vb = vv + (size_t)bh * NS * DD;

    // Gradient accumulators (registers)
    // dW1a: d = rg*8+i (i<8), e = lane+32*j (j<8)
    // dW2a: e = rg*32+je (je<32), o = lane+32*jo (jo<2)
    float dW1a[8][8];
    float dW2a[32][2];

    for (int it = 0; it < NITN; ++it) {
        #pragma unroll
        for (int i = 0; i < 8; ++i)
            #pragma unroll
            for (int j = 0; j < 8; ++j) dW1a[i][j] = 0.0f;
        #pragma unroll
        for (int je = 0; je < 32; ++je) { dW2a[je][0] = 0.0f; dW2a[je][1] = 0.0f; }

        for (int mt = 0; mt < NTILE; ++mt) {
            const int rowbase = it * CHUNK + mt * MT;
            // Load X (k) and Y (v) tiles: contiguous 2048 floats each
            #pragma unroll
            for (int r = 0; r < 8; ++r) {
                sX[tid + 256 * r] = kb[(size_t)rowbase * DD + tid + 256 * r];
                sY[tid + 256 * r] = vb[(size_t)rowbase * DD + tid + 256 * r];
            }
            __syncthreads();

            // ---- G1: Z[32][256] = X @ W1 ; rows m=rg*4+i, cols e=lane+32*j
            {
                float acc[4][8];
                #pragma unroll
                for (int i = 0; i < 4; ++i)
                    #pragma unroll
                    for (int j = 0; j < 8; ++j) acc[i][j] = 0.0f;
                #pragma unroll 4
                for (int d = 0; d < DD; ++d) {
                    float a[4];
                    #pragma unroll
                    for (int i = 0; i < 4; ++i) a[i] = sX[(rg * 4 + i) * DD + d];
                    float b[8];
                    #pragma unroll
                    for (int j = 0; j < 8; ++j) b[j] = sW1[d * HI + lane + 32 * j];
                    #pragma unroll
                    for (int i = 0; i < 4; ++i)
                        #pragma unroll
                        for (int j = 0; j < 8; ++j)
                            acc[i][j] = fmaf(a[i], b[j], acc[i][j]);
                }
                #pragma unroll
                for (int i = 0; i < 4; ++i)
                    #pragma unroll
                    for (int j = 0; j < 8; ++j) {
                        float gp;
                        float hv = gelu_fwd_bwd(acc[i][j], &gp);
                        int idx = (rg * 4 + i) * HI + lane + 32 * j;
                        sZ[idx]  = hv;     // store H
                        sGp[idx] = gp;     // store gelu'
                    }
            }
            __syncthreads();

            // ---- G2: E[32][64] = (H @ W2 - Y) * INV_SC
            {
                float acc[4][2];
                #pragma unroll
                for (int i = 0; i < 4; ++i) { acc[i][0] = 0.0f; acc[i][1] = 0.0f; }
                #pragma unroll 4
                for (int e = 0; e < HI; ++e) {
                    float a[4];
                    #pragma unroll
                    for (int i = 0; i < 4; ++i) a[i] = sZ[(rg * 4 + i) * HI + e];
                    float b0 = sW2[e * 65 + lane];
                    float b1 = sW2[e * 65 + lane + 32];
                    #pragma unroll
                    for (int i = 0; i < 4; ++i) {
                        acc[i][0] = fmaf(a[i], b0, acc[i][0]);
                        acc[i][1] = fmaf(a[i], b1, acc[i][1]);
                    }
                }
                #pragma unroll
                for (int i = 0; i < 4; ++i) {
                    int m = rg * 4 + i;
                    sE[m * DD + lane]      = (acc[i][0] - sY[m * DD + lane])      * INV_SC;
                    sE[m * DD + lane + 32] = (acc[i][1] - sY[m * DD + lane + 32]) * INV_SC;
                }
            }
            __syncthreads();

            // ---- G3: dW2 += H^T @ E  (K = 32 rows)
            #pragma unroll 2
            for (int m = 0; m < MT; ++m) {
                float b0 = sE[m * DD + lane];
                float b1 = sE[m * DD + lane + 32];
                #pragma unroll
                for (int je = 0; je < 32; ++je) {
                    float a = sZ[m * HI + rg * 32 + je];
                    dW2a[je][0] = fmaf(a, b0, dW2a[je][0]);
                    dW2a[je][1] = fmaf(a, b1, dW2a[je][1]);
                }
            }

            // ---- G4: dH[32][256] = E @ W2^T ; dZ = dH * gelu'
            {
                float dz[4][8];
                #pragma unroll
                for (int i = 0; i < 4; ++i)
                    #pragma unroll
                    for (int j = 0; j < 8; ++j) dz[i][j] = 0.0f;
                #pragma unroll 4
                for (int o = 0; o < DD; ++o) {
                    float a[4];
                    #pragma unroll
                    for (int i = 0; i < 4; ++i) a[i] = sE[(rg * 4 + i) * DD + o];
                    float b[8];
                    #pragma unroll
                    for (int j = 0; j < 8; ++j) b[j] = sW2[(lane + 32 * j) * 65 + o];
                    #pragma unroll
                    for (int i = 0; i < 4; ++i)
                        #pragma unroll
                        for (int j = 0; j < 8; ++j)
                            dz[i][j] = fmaf(a[i], b[j], dz[i][j]);
                }
                __syncthreads();   // G3 finished reading sZ(H); now overwrite with dZ
                #pragma unroll
                for (int i = 0; i < 4; ++i)
                    #pragma unroll
                    for (int j = 0; j < 8; ++j) {
                        int idx = (rg * 4 + i) * HI + lane + 32 * j;
                        sZ[idx] = dz[i][j] * sGp[idx];
                    }
            }
            __syncthreads();

            // ---- G5: dW1 += X^T @ dZ  (K = 32 rows)
            #pragma unroll 2
            for (int m = 0; m < MT; ++m) {
                float a[8];
                #pragma unroll
                for (int i = 0; i < 8; ++i) a[i] = sX[m * DD + rg * 8 + i];
                float b[8];
                #pragma unroll
                for (int j = 0; j < 8; ++j) b[j] = sZ[m * HI + lane + 32 * j];
                #pragma unroll
                for (int i = 0; i < 8; ++i)
                    #pragma unroll
                    for (int j = 0; j < 8; ++j)
                        dW1a[i][j] = fmaf(a[i], b[j], dW1a[i][j]);
            }
            __syncthreads();   // protect sX/sY/sZ before next tile
        }

        // ---- SGD update (lr = 1.0)
        #pragma unroll
        for (int i = 0; i < 8; ++i)
            #pragma unroll
            for (int j = 0; j < 8; ++j)
                sW1[(rg * 8 + i) * HI + lane + 32 * j] -= dW1a[i][j];
        #pragma unroll
        for (int je = 0; je < 32; ++je) {
            sW2[(rg * 32 + je) * 65 + lane]      -= dW2a[je][0];
            sW2[(rg * 32 + je) * 65 + lane + 32] -= dW2a[je][1];
        }
        __syncthreads();
    }

    // Store final adapted weights to scratch
    float* gw = g_W + (size_t)bh * (DD * HI + HI * DD);
    for (int i = tid; i < DD * HI; i += 256) gw[i] = sW1[i];
    for (int i = tid; i < HI * DD; i += 256) {
        int e = i >> 6, o = i & 63;
        gw[DD * HI + i] = sW2[e * 65 + o];
    }
}

// ---------------- Eval: out = enc(final_params, q), 64-row tiles ------------
// SMEM: sW1 [64][256] @0 (16384), sW2 [256][64] @16384 (16384),
//       sQ [64][64] @32768 (4096), sH [64][256] @36864 (16384) -> 53248 floats
__global__ __launch_bounds__(256, 1)
void ttt_eval_kernel(const float* __restrict__ qq, float* __restrict__ out) {
    extern __shared__ float sm[];
    float* sW1 = sm;
    float* sW2 = sm + 16384;
    float* sQ  = sm + 32768;
    float* sH  = sm + 36864;

    const int tile = blockIdx.x;     // 0..31
    const int bh   = blockIdx.y;     // 0..127
    const int b    = bh >> 4;
    const int h    = bh & 15;
    const int tid  = threadIdx.x;
    const int lane = tid & 31;
    const int rg   = tid >> 5;

    const float* gw = g_W + (size_t)bh * (DD * HI + HI * DD);
    for (int i = tid; i < DD * HI; i += 256) sW1[i] = gw[i];
    for (int i = tid; i < HI * DD; i += 256) sW2[i] = gw[DD * HI + i];

    const float* qb = qq + ((size_t)bh * NS + tile * 64) * DD;
    for (int i = tid; i < 64 * DD; i += 256) sQ[i] = qb[i];
    __syncthreads();

    // Z[64][256] = Q @ W1 ; rows m=rg*8+i, cols e=lane+32*j
    {
        float acc[8][8];
        #pragma unroll
        for (int i = 0; i < 8; ++i)
            #pragma unroll
            for (int j = 0; j < 8; ++j) acc[i][j] = 0.0f;
        #pragma unroll 4
        for (int d = 0; d < DD; ++d) {
            float a[8];
            #pragma unroll
            for (int i = 0; i < 8; ++i) a[i] = sQ[(rg * 8 + i) * DD + d];
            float bvals[8];
            #pragma unroll
            for (int j = 0; j < 8; ++j) bvals[j] = sW1[d * HI + lane + 32 * j];
            #pragma unroll
            for (int i = 0; i < 8; ++i)
                #pragma unroll
                for (int j = 0; j < 8; ++j)
                    acc[i][j] = fmaf(a[i], bvals[j], acc[i][j]);
        }
        #pragma unroll
        for (int i = 0; i < 8; ++i)
            #pragma unroll
            for (int j = 0; j < 8; ++j)
                sH[(rg * 8 + i) * HI + lane + 32 * j] = gelu_f(acc[i][j]);
    }
    __syncthreads();

    // O[64][64] = H @ W2 ; rows m=rg*8+i, cols o=lane+32*jo
    {
        float acc[8][2];
        #pragma unroll
        for (int i = 0; i < 8; ++i) { acc[i][0] = 0.0f; acc[i][1] = 0.0f; }
        #pragma unroll 4
        for (int e = 0; e < HI; ++e) {
            float a[8];
            #pragma unroll
            for (int i = 0; i < 8; ++i) a[i] = sH[(rg * 8 + i) * HI + e];
            float b0 = sW2[e * DD + lane];
            float b1 = sW2[e * DD + lane + 32];
            #pragma unroll
            for (int i = 0; i < 8; ++i) {
                acc[i][0] = fmaf(a[i], b0, acc[i][0]);
                acc[i][1] = fmaf(a[i], b1, acc[i][1]);
            }
        }
        // out[b, n, h*64 + o], n = tile*64 + m
        #pragma unroll
        for (int i = 0; i < 8; ++i) {
            int n = tile * 64 + rg * 8 + i;
            size_t base = ((size_t)b * NS + n) * (NH * DD) + h * DD;
            out[base + lane]      = acc[i][0];
            out[base + lane + 32] = acc[i][1];
        }
    }
}

extern "C" void kernel_launch(void* const* d_in, const int* in_sizes, int n_in,
                              void* d_out, int out_size) {
    const float* q  = (const float*)d_in[0];
    const float* k  = (const float*)d_in[1];
    const float* v  = (const float*)d_in[2];
    const float* W1 = (const float*)d_in[3];
    const float* W2 = (const float*)d_in[4];
    float* out = (float*)d_out;

    cudaFuncSetAttribute(ttt_train_kernel,
                         cudaFuncAttributeMaxDynamicSharedMemorySize, TRAIN_SMEM_BYTES);
    cudaFuncSetAttribute(ttt_eval_kernel,
                         cudaFuncAttributeMaxDynamicSharedMemorySize, EVAL_SMEM_BYTES);

    ttt_train_kernel<<<NB * NH, 256, TRAIN_SMEM_BYTES>>>(k, v, W1, W2);
    ttt_eval_kernel<<<dim3(NS / 64, NB * NH), 256, EVAL_SMEM_BYTES>>>(q, out);
}